// round 7
// baseline (speedup 1.0000x reference)
#include <cuda_runtime.h>
#include <cuda_bf16.h>
#include <math.h>
#include <stdint.h>

#define N_  4
#define T_  4096
#define D_  1024
#define H_  1536
#define M_  (N_*T_)       // 16384 rows
#define G2H (2*H_)        // 3072
#define TC  128           // scan chunk length
#define NC  (T_/TC)       // 32 chunks

// -------- scratch (device globals; no allocation allowed) --------
__device__ __align__(256) float g_gx  [(size_t)M_*G2H];   // GEMM1 out; gate half = gelu(gate)
__device__ __align__(256) float g_alpha[(size_t)M_*H_];
__device__ __align__(256) float g_xs  [(size_t)M_*H_];
__device__ __align__(256) float g_cA  [N_*NC*H_];
__device__ __align__(256) float g_cB  [N_*NC*H_];
// bf16 hi/lo planes
__device__ __align__(256) __nv_bfloat16 g_xh [(size_t)M_*D_];
__device__ __align__(256) __nv_bfloat16 g_xl [(size_t)M_*D_];
__device__ __align__(256) __nv_bfloat16 g_xbh[(size_t)M_*H_];   // conv out planes
__device__ __align__(256) __nv_bfloat16 g_xbl[(size_t)M_*H_];
__device__ __align__(256) __nv_bfloat16 g_yh [(size_t)M_*H_];   // gelu(gate)*h planes
__device__ __align__(256) __nv_bfloat16 g_yl [(size_t)M_*H_];
__device__ __align__(256) __nv_bfloat16 g_wih[(size_t)G2H*D_];  // W_in planes
__device__ __align__(256) __nv_bfloat16 g_wil[(size_t)G2H*D_];
__device__ __align__(256) __nv_bfloat16 g_wgh[(size_t)G2H*H_];  // W_g planes (rows permuted)
__device__ __align__(256) __nv_bfloat16 g_wgl[(size_t)G2H*H_];
__device__ __align__(256) __nv_bfloat16 g_woh[(size_t)D_*H_];   // W_out planes
__device__ __align__(256) __nv_bfloat16 g_wol[(size_t)D_*H_];

// ======================= helpers =======================
__device__ __forceinline__ uint32_t smem_u32(const void* p) {
    uint32_t a;
    asm("{ .reg .u64 t; cvta.to.shared.u64 t, %1; cvt.u32.u64 %0, t; }" : "=r"(a) : "l"(p));
    return a;
}
__device__ __forceinline__ void ldmx4(uint32_t* r, uint32_t a) {
    asm volatile("ldmatrix.sync.aligned.m8n8.x4.shared.b16 {%0,%1,%2,%3}, [%4];"
        : "=r"(r[0]), "=r"(r[1]), "=r"(r[2]), "=r"(r[3]) : "r"(a));
}
__device__ __forceinline__ void mma16816(float* d, const uint32_t* a, const uint32_t* b) {
    asm volatile("mma.sync.aligned.m16n8k16.row.col.f32.bf16.bf16.f32 "
        "{%0,%1,%2,%3}, {%4,%5,%6,%7}, {%8,%9}, {%0,%1,%2,%3};"
        : "+f"(d[0]), "+f"(d[1]), "+f"(d[2]), "+f"(d[3])
        : "r"(a[0]), "r"(a[1]), "r"(a[2]), "r"(a[3]), "r"(b[0]), "r"(b[1]));
}
__device__ __forceinline__ void cpa16(uint32_t dst, const void* src) {
    asm volatile("cp.async.cg.shared.global [%0], [%1], 16;" :: "r"(dst), "l"(src));
}
#define CP_COMMIT() asm volatile("cp.async.commit_group;" ::: "memory")
#define CP_WAIT0()  asm volatile("cp.async.wait_group 0;" ::: "memory")
__device__ __forceinline__ float sigmoidf_(float v) { return 1.f / (1.f + expf(-v)); }
__device__ __forceinline__ void split_bf(float v, __nv_bfloat16& h, __nv_bfloat16& l) {
    h = __float2bfloat16(v);
    l = __float2bfloat16(v - __bfloat162float(h));
}

// ================== bf16x3 mma GEMM (cp.async, prepacked planes) ==================
// Block tile 128x128x32, 256 threads (8 warps: 4(m) x 2(n)), warp tile 32x64.
// SMEM rows padded to 80B. 2-stage (81920B -> 2 CTAs/SM). No conversions in loop.
#define BKB    80
#define AH_OFF 0
#define AL_OFF 10240
#define BH_OFF 20480
#define BL_OFF 30720
#define STAGE  40960
#define GEMM_SMEM (2*STAGE)   // 81920

__device__ __forceinline__ void issue_chunk(
    uint32_t stg, int tid, int k0, int K,
    const __nv_bfloat16* __restrict__ Ah, const __nv_bfloat16* __restrict__ Al,
    const __nv_bfloat16* __restrict__ Bh, const __nv_bfloat16* __restrict__ Bl)
{
    const int seg = tid & 3;
    const int r0 = tid >> 2;          // 0..63
#pragma unroll
    for (int it = 0; it < 2; it++) {
        const int row = r0 + it * 64;
        const size_t go = (size_t)row * K + k0 + seg * 8;
        const uint32_t so = (uint32_t)(row * BKB + seg * 16);
        cpa16(stg + AH_OFF + so, Ah + go);
        cpa16(stg + AL_OFF + so, Al + go);
        cpa16(stg + BH_OFF + so, Bh + go);
        cpa16(stg + BL_OFF + so, Bl + go);
    }
}

__device__ __forceinline__ void compute_kt(float acc[2][8][4], uint32_t sa, uint32_t sbb, int kt) {
    uint32_t ah[2][4], al[2][4], bh[4][4], bl[4][4];
#pragma unroll
    for (int mt = 0; mt < 2; mt++) {
        ldmx4(ah[mt], sa + mt * (16 * BKB) + kt * 32);
        ldmx4(al[mt], sa + AL_OFF + mt * (16 * BKB) + kt * 32);
    }
#pragma unroll
    for (int n2 = 0; n2 < 4; n2++) {
        ldmx4(bh[n2], sbb + n2 * (16 * BKB) + kt * 32);
        ldmx4(bl[n2], sbb + (BL_OFF - BH_OFF) + n2 * (16 * BKB) + kt * 32);
    }
#pragma unroll
    for (int mt = 0; mt < 2; mt++)
#pragma unroll
        for (int nt = 0; nt < 8; nt++) {
            uint32_t* bph = &bh[nt >> 1][(nt & 1) * 2];
            uint32_t* bpl = &bl[nt >> 1][(nt & 1) * 2];
            mma16816(acc[mt][nt], ah[mt], bph);
            mma16816(acc[mt][nt], ah[mt], bpl);
            mma16816(acc[mt][nt], al[mt], bph);
        }
}

// EPI: 0 = plain, 1 = gelu on cols < H_, 2 = fused ew (alpha/xs)
template<int EPI>
__global__ __launch_bounds__(256)
void gemm_mma(const __nv_bfloat16* __restrict__ Ah, const __nv_bfloat16* __restrict__ Al,
              const __nv_bfloat16* __restrict__ Bh, const __nv_bfloat16* __restrict__ Bl,
              float* __restrict__ C,
              const __nv_bfloat16* __restrict__ xbh, const __nv_bfloat16* __restrict__ xbl,
              const float* __restrict__ bg, const float* __restrict__ fbase,
              float* __restrict__ alpha_o, float* __restrict__ xs_o,
              int K, int ldc)
{
    extern __shared__ char sm[];
    const int tid = threadIdx.x;
    const int lid = tid & 31, wid = tid >> 5;
    const int wm = wid >> 1, wn = wid & 1;
    const int bm = blockIdx.y * 128;
    const int bn = blockIdx.x * 128;

    const __nv_bfloat16* Ahb = Ah + (size_t)bm * K;
    const __nv_bfloat16* Alb = Al + (size_t)bm * K;
    const __nv_bfloat16* Bhb = Bh + (size_t)bn * K;
    const __nv_bfloat16* Blb = Bl + (size_t)bn * K;

    float acc[2][8][4];
#pragma unroll
    for (int i = 0; i < 2; i++)
#pragma unroll
        for (int j = 0; j < 8; j++)
#pragma unroll
            for (int q = 0; q < 4; q++) acc[i][j][q] = 0.f;

    const uint32_t sb = smem_u32(sm);
    const uint32_t a_base = sb + (uint32_t)((wm * 32 + (lid & 15)) * BKB + ((lid >> 4) & 1) * 16);
    const uint32_t b_base = sb + BH_OFF +
        (uint32_t)((wn * 64 + (lid & 7) + ((lid >> 4) & 1) * 8) * BKB + ((lid >> 3) & 1) * 16);

    issue_chunk(sb, tid, 0, K, Ahb, Alb, Bhb, Blb);
    CP_COMMIT();

    const int KT = K >> 5;
    for (int c = 0; c < KT; c++) {
        const int cur = c & 1;
        CP_WAIT0();
        __syncthreads();
        if (c + 1 < KT) {
            issue_chunk(sb + ((c + 1) & 1) * STAGE, tid, (c + 1) * 32, K, Ahb, Alb, Bhb, Blb);
            CP_COMMIT();
        }
        const uint32_t sa  = a_base + cur * STAGE;
        const uint32_t sbb = b_base + cur * STAGE;
        compute_kt(acc, sa, sbb, 0);
        compute_kt(acc, sa, sbb, 1);
    }

    const int r0 = bm + wm * 32 + (lid >> 2);

    if (EPI == 2) {
        // fused ew: output cols interleaved (forget_h, inp_h); h = (bn + col)/2
        const int hbase = (bn >> 1) + wn * 32 + (lid & 3);
        float sp8[8], bgf[8], bgi[8];
#pragma unroll
        for (int nt = 0; nt < 8; nt++) {
            int h = hbase + nt * 4;
            float fb = fbase[h];
            sp8[nt] = fmaxf(fb, 0.f) + log1pf(expf(-fabsf(fb)));
            bgf[nt] = bg[h]; bgi[nt] = bg[H_ + h];
        }
#pragma unroll
        for (int mt = 0; mt < 2; mt++) {
            int row = r0 + mt * 16;
#pragma unroll
            for (int nt = 0; nt < 8; nt++) {
                int h = hbase + nt * 4;
#pragma unroll
                for (int half = 0; half < 2; half++) {
                    int rr = row + half * 8;
                    float forget = acc[mt][nt][half * 2 + 0] + bgf[nt];
                    float inp    = acc[mt][nt][half * 2 + 1] + bgi[nt];
                    float a = expf(-8.f * sp8[nt] * sigmoidf_(forget));
                    float beta = sqrtf(1.f - a * a + 1e-6f);
                    size_t ix = (size_t)rr * H_ + h;
                    float xb = __bfloat162float(xbh[ix]) + __bfloat162float(xbl[ix]);
                    alpha_o[ix] = a;
                    xs_o[ix] = beta * sigmoidf_(inp) * xb;
                }
            }
        }
        return;
    }

    const bool dg = (EPI == 1) && (bn < H_);
    const int cbase = bn + wn * 64 + (lid & 3) * 2;
#pragma unroll
    for (int mt = 0; mt < 2; mt++) {
        const int row = r0 + mt * 16;
#pragma unroll
        for (int nt = 0; nt < 8; nt++) {
            const int col = cbase + nt * 8;
            float2 v0 = make_float2(acc[mt][nt][0], acc[mt][nt][1]);
            float2 v1 = make_float2(acc[mt][nt][2], acc[mt][nt][3]);
            if (dg) {
                v0.x = 0.5f * v0.x * (1.f + erff(v0.x * 0.70710678118654752f));
                v0.y = 0.5f * v0.y * (1.f + erff(v0.y * 0.70710678118654752f));
                v1.x = 0.5f * v1.x * (1.f + erff(v1.x * 0.70710678118654752f));
                v1.y = 0.5f * v1.y * (1.f + erff(v1.y * 0.70710678118654752f));
            }
            *(float2*)(C + (size_t)row * ldc + col) = v0;
            *(float2*)(C + (size_t)(row + 8) * ldc + col) = v1;
        }
    }
}

// -------- pack fp32 -> bf16 hi/lo planes --------
__global__ void pack2(const float* __restrict__ s, __nv_bfloat16* __restrict__ hi,
                      __nv_bfloat16* __restrict__ lo, long long n4)
{
    long long i = (long long)blockIdx.x * blockDim.x + threadIdx.x;
    if (i >= n4) return;
    float4 f = *(const float4*)(s + i * 4);
    __nv_bfloat16 h[4], l[4];
    split_bf(f.x, h[0], l[0]); split_bf(f.y, h[1], l[1]);
    split_bf(f.z, h[2], l[2]); split_bf(f.w, h[3], l[3]);
    *(uint2*)(hi + i * 4) = *(uint2*)h;
    *(uint2*)(lo + i * 4) = *(uint2*)l;
}

// pack W_g with row permutation: packed row r = src row (r&1)*H_ + (r>>1)
__global__ void pack_wg(const float* __restrict__ s, __nv_bfloat16* __restrict__ hi,
                        __nv_bfloat16* __restrict__ lo)
{
    int idx = blockIdx.x * blockDim.x + threadIdx.x;   // over G2H * H_/4
    if (idx >= G2H * (H_ / 4)) return;
    int r = idx / (H_ / 4);
    int c = (idx % (H_ / 4)) * 4;
    int sr = (r & 1) * H_ + (r >> 1);
    float4 f = *(const float4*)(s + (size_t)sr * H_ + c);
    __nv_bfloat16 h[4], l[4];
    split_bf(f.x, h[0], l[0]); split_bf(f.y, h[1], l[1]);
    split_bf(f.z, h[2], l[2]); split_bf(f.w, h[3], l[3]);
    *(uint2*)(hi + (size_t)r * H_ + c) = *(uint2*)h;
    *(uint2*)(lo + (size_t)r * H_ + c) = *(uint2*)l;
}

// -------- depthwise causal conv K=4 -> bf16 planes --------
__global__ void conv_kernel(const float* __restrict__ cw, const float* __restrict__ cb)
{
    long long idx = (long long)blockIdx.x * blockDim.x + threadIdx.x;
    if (idx >= (long long)M_ * H_) return;
    int h = (int)(idx % H_);
    long long m = idx / H_;
    int t = (int)(m % T_);
    long long n = m / T_;
    float acc = cb[h];
    const float* w = cw + h * 4;
#pragma unroll
    for (int k = 0; k < 4; k++) {
        int tt = t - 3 + k;
        if (tt >= 0)
            acc = fmaf(w[k], g_gx[((size_t)(n * T_ + tt)) * G2H + H_ + h], acc);
    }
    __nv_bfloat16 hi, lo;
    split_bf(acc, hi, lo);
    g_xbh[idx] = hi;
    g_xbl[idx] = lo;
}

// -------- chunked linear scan --------
__global__ void scan_p1()
{
    int h = blockIdx.x * 128 + threadIdx.x;
    int c = blockIdx.y, n = blockIdx.z;
    size_t base = ((size_t)(n * T_ + c * TC)) * H_ + h;
    float A = 1.f, Bv = 0.f;
#pragma unroll 4
    for (int t = 0; t < TC; t++) {
        float a = g_alpha[base + (size_t)t * H_];
        float x = g_xs   [base + (size_t)t * H_];
        Bv = fmaf(a, Bv, x);
        A *= a;
    }
    int ci = (n * NC + c) * H_ + h;
    g_cA[ci] = A;
    g_cB[ci] = Bv;
}

__global__ void scan_p2()
{
    int h = blockIdx.x * 128 + threadIdx.x;
    int n = blockIdx.y;
    float carry = 0.f;
    for (int c = 0; c < NC; c++) {
        int i = (n * NC + c) * H_ + h;
        float a = g_cA[i], b = g_cB[i];
        g_cB[i] = carry;
        carry = fmaf(a, carry, b);
    }
}

__global__ void scan_p3()   // replay; write (gelu(gate)*h) as bf16 planes
{
    int h = blockIdx.x * 128 + threadIdx.x;
    int c = blockIdx.y, n = blockIdx.z;
    size_t base  = ((size_t)(n * T_ + c * TC)) * H_ + h;
    size_t gbase = ((size_t)(n * T_ + c * TC)) * G2H + h;
    float hp = g_cB[(n * NC + c) * H_ + h];
#pragma unroll 4
    for (int t = 0; t < TC; t++) {
        float a = g_alpha[base + (size_t)t * H_];
        float x = g_xs   [base + (size_t)t * H_];
        hp = fmaf(a, hp, x);
        float g = g_gx[gbase + (size_t)t * G2H];   // gelu(gate)
        float v = hp * g;
        __nv_bfloat16 hi, lo;
        split_bf(v, hi, lo);
        g_yh[base + (size_t)t * H_] = hi;
        g_yl[base + (size_t)t * H_] = lo;
    }
}

// -------- launch --------
extern "C" void kernel_launch(void* const* d_in, const int* in_sizes, int n_in,
                              void* d_out, int out_size)
{
    const float* x      = (const float*)d_in[0];
    const float* W_in   = (const float*)d_in[1];
    const float* conv_w = (const float*)d_in[2];
    const float* conv_b = (const float*)d_in[3];
    const float* W_g    = (const float*)d_in[4];
    const float* b_g    = (const float*)d_in[5];
    const float* fbase  = (const float*)d_in[6];
    const float* W_out  = (const float*)d_in[7];
    float* out = (float*)d_out;

    float *gx, *alp, *xs;
    __nv_bfloat16 *xh, *xl, *xbh, *xbl, *yh, *yl, *wih, *wil, *wgh, *wgl, *woh, *wol;
    cudaGetSymbolAddress((void**)&gx,  g_gx);
    cudaGetSymbolAddress((void**)&alp, g_alpha);
    cudaGetSymbolAddress((void**)&xs,  g_xs);
    cudaGetSymbolAddress((void**)&xh,  g_xh);
    cudaGetSymbolAddress((void**)&xl,  g_xl);
    cudaGetSymbolAddress((void**)&xbh, g_xbh);
    cudaGetSymbolAddress((void**)&xbl, g_xbl);
    cudaGetSymbolAddress((void**)&yh,  g_yh);
    cudaGetSymbolAddress((void**)&yl,  g_yl);
    cudaGetSymbolAddress((void**)&wih, g_wih);
    cudaGetSymbolAddress((void**)&wil, g_wil);
    cudaGetSymbolAddress((void**)&wgh, g_wgh);
    cudaGetSymbolAddress((void**)&wgl, g_wgl);
    cudaGetSymbolAddress((void**)&woh, g_woh);
    cudaGetSymbolAddress((void**)&wol, g_wol);

    cudaFuncSetAttribute(gemm_mma<0>, cudaFuncAttributeMaxDynamicSharedMemorySize, GEMM_SMEM);
    cudaFuncSetAttribute(gemm_mma<1>, cudaFuncAttributeMaxDynamicSharedMemorySize, GEMM_SMEM);
    cudaFuncSetAttribute(gemm_mma<2>, cudaFuncAttributeMaxDynamicSharedMemorySize, GEMM_SMEM);

    const long long tot = (long long)M_ * H_;
    const int EB = 256;
    const int eg = (int)((tot + EB - 1) / EB);

    // 0) pack operands to bf16 hi/lo planes
    pack2<<<(int)(((long long)M_*D_/4 + 255)/256), 256>>>(x, xh, xl, (long long)M_*D_/4);
    pack2<<<(G2H*D_/4 + 255)/256, 256>>>(W_in, wih, wil, (long long)G2H*D_/4);
    pack_wg<<<(G2H*(H_/4) + 255)/256, 256>>>(W_g, wgh, wgl);
    pack2<<<(D_*H_/4 + 255)/256, 256>>>(W_out, woh, wol, (long long)D_*H_/4);

    // 1) gx = x @ W_in^T; gelu fused on gate half
    gemm_mma<1><<<dim3(G2H/128, M_/128), 256, GEMM_SMEM>>>(
        xh, xl, wih, wil, gx, nullptr, nullptr, nullptr, nullptr, nullptr, nullptr, D_, G2H);
    // 2) depthwise causal conv -> xb planes
    conv_kernel<<<eg, EB>>>(conv_w, conv_b);
    // 3) fused ew GEMM -> alpha, xs
    gemm_mma<2><<<dim3(G2H/128, M_/128), 256, GEMM_SMEM>>>(
        xbh, xbl, wgh, wgl, nullptr, xbh, xbl, b_g, fbase, alp, xs, H_, 0);
    // 4) scan
    scan_p1<<<dim3(H_/128, NC, N_), 128>>>();
    scan_p2<<<dim3(H_/128, N_), 128>>>();
    scan_p3<<<dim3(H_/128, NC, N_), 128>>>();
    // 5) out = y @ W_out^T
    gemm_mma<0><<<dim3(D_/128, M_/128), 256, GEMM_SMEM>>>(
        yh, yl, woh, wol, out, nullptr, nullptr, nullptr, nullptr, nullptr, nullptr, H_, D_);
}